// round 17
// baseline (speedup 1.0000x reference)
#include <cuda_runtime.h>
#include <math.h>

// Problem dims
#define BB 128
#define SS 1024
#define QMAX 5001          // q ids 0..5000
#define MSLOT 64
#define KDIM 128
#define VDIM 256
#define FDIM 128
#define NT 131072          // BB*SS

typedef unsigned long long ull;

// ---------------- scratch (static device arrays: no allocation) -------------
__device__ float g_Wtab[QMAX * MSLOT];          // softmax(qe @ K^T) per q
__device__ float g_bvE2[512];                   // b_value@[We|Wa] + [b_erase|b_add]
__device__ float g_EAtab[QMAX * 4 * 512];       // [q][r][ erase(256) | add(256) ]
__device__ float g_QStab[QMAX * FDIM];          // qe @ W_summary[256:384] + b_summary
__device__ float g_betatab[QMAX * 3];           // qe @ W_beta + b_beta
__device__ float g_qdtab[QMAX];                 // qe @ W_disc[128:256]
__device__ float g_read[(size_t)NT * VDIM];     // per-step memory reads
__device__ float g_thdp[(size_t)NT * 2];        // fused (summary@W_theta, summary@W_disc)

// ---------------- packed f32x2 helpers --------------------------------------
__device__ __forceinline__ ull pack2(float lo, float hi) {
    ull d; asm("mov.b64 %0, {%1, %2};" : "=l"(d) : "f"(lo), "f"(hi)); return d;
}
__device__ __forceinline__ void unpack2(ull v, float& lo, float& hi) {
    asm("mov.b64 {%0, %1}, %2;" : "=f"(lo), "=f"(hi) : "l"(v));
}
__device__ __forceinline__ ull fma2(ull a, ull b, ull c) {
    ull d; asm("fma.rn.f32x2 %0, %1, %2, %3;" : "=l"(d) : "l"(a), "l"(b), "l"(c));
    return d;
}

// 1-MUFU activations
__device__ __forceinline__ float tanh_(float x) {
    float y; asm("tanh.approx.f32 %0, %1;" : "=f"(y) : "f"(x)); return y;
}
__device__ __forceinline__ float sigmoid_(float x) {
    return fmaf(0.5f, tanh_(0.5f * x), 0.5f);
}
__device__ __forceinline__ float softplusf_(float x) {
    return fmaxf(x, 0.0f) + log1pf(expf(-fabsf(x)));
}

// ---------------- K1: wtab + perq (key staged in padded smem); last blk: bv --
#define QPER 8
#define WTAB_BLOCKS ((QMAX + QPER - 1) / QPER)   // 626
__global__ void __launch_bounds__(128) wtab_perq_kernel(const float* __restrict__ qe_table,
                                                        const float* __restrict__ key_memory,
                                                        const float* __restrict__ W_summary,
                                                        const float* __restrict__ b_summary,
                                                        const float* __restrict__ W_beta,
                                                        const float* __restrict__ b_beta,
                                                        const float* __restrict__ W_disc,
                                                        const float* __restrict__ b_value,
                                                        const float* __restrict__ W_erase,
                                                        const float* __restrict__ W_add,
                                                        const float* __restrict__ b_erase,
                                                        const float* __restrict__ b_add) {
    const int t = threadIdx.x;
    if (blockIdx.x == WTAB_BLOCKS) {   // bv role: bvE2 + EAtab[q=0]
        for (int j = t; j < 512; j += 128) {
            const float* W = (j < 256) ? (W_erase + j) : (W_add + (j - 256));
            float a = 0.0f;
            for (int k = 0; k < 256; k++) a = fmaf(b_value[k], W[k * 256], a);
            float bias = (j < 256) ? b_erase[j] : b_add[j - 256];
            float x = a + bias;
            g_bvE2[j] = x;
            float act = (j < 256) ? sigmoid_(x) : tanh_(x);
            #pragma unroll
            for (int rr = 0; rr < 4; rr++) g_EAtab[(size_t)rr * 512 + j] = act;
        }
        return;
    }
    __shared__ float skey[MSLOT * 129];   // padded, conflict-free
    __shared__ float qe[KDIM];
    __shared__ float sh_d[MSLOT];
    __shared__ float sh_e[MSLOT];

    for (int i = t; i < MSLOT * KDIM; i += 128) {
        int row = i >> 7, col = i & 127;
        skey[row * 129 + col] = key_memory[i];
    }

    int q0 = blockIdx.x * QPER;
    int qend = min(q0 + QPER, QMAX);
    float bsum_t = b_summary[t];

    for (int q = q0; q < qend; q++) {
        __syncthreads();
        qe[t] = qe_table[q * KDIM + t];
        __syncthreads();
        if (t < MSLOT) {
            float d = 0.0f;
            #pragma unroll 8
            for (int k = 0; k < KDIM; k++) d = fmaf(qe[k], skey[t * 129 + k], d);
            sh_d[t] = d;
        }
        __syncthreads();
        if (t < MSLOT) {
            float mx = -1e30f;
            #pragma unroll 8
            for (int i = 0; i < MSLOT; i++) mx = fmaxf(mx, sh_d[i]);
            sh_e[t] = expf(sh_d[t] - mx);
        }
        __syncthreads();
        if (t < MSLOT) {
            float sum = 0.0f;
            #pragma unroll 8
            for (int i = 0; i < MSLOT; i++) sum += sh_e[i];
            g_Wtab[q * MSLOT + t] = sh_e[t] / sum;
        }
        {
            float acc = bsum_t;
            #pragma unroll 8
            for (int dd = 0; dd < KDIM; dd++)
                acc = fmaf(qe[dd], W_summary[(256 + dd) * FDIM + t], acc);
            g_QStab[q * FDIM + t] = acc;
        }
        if (t < 3) {
            float a = b_beta[t];
            for (int dd = 0; dd < KDIM; dd++) a = fmaf(qe[dd], W_beta[dd * 3 + t], a);
            g_betatab[q * 3 + t] = a;
        } else if (t == 4) {
            float a = 0.0f;
            for (int dd = 0; dd < KDIM; dd++) a = fmaf(qe[dd], W_disc[128 + dd], a);
            g_qdtab[q] = a;
        }
    }
}

// ---------------- K2: fused PP-GEMM + EA table (double-buffered smem) --------
__global__ void __launch_bounds__(256, 2) ppea_kernel(const float* __restrict__ Wv,
                                                      const float* __restrict__ We,
                                                      const float* __restrict__ Wa) {
    const int K = 256;
    __shared__ float As1[2][8][128];  // duplicated pairs: 64 rows
    __shared__ float As2[2][8][128];
    __shared__ float Bs[2][8][128];
    int tid = threadIdx.x;
    int row0 = blockIdx.y * 64, col0 = blockIdx.x * 128;
    int lrow = (tid & 127) >> 1, ak4 = (tid & 1) * 4;
    int bK = tid >> 5, bCol = (tid & 31) * 4;
    int tx = tid & 15, ty = tid >> 4;
    ull acc1[4][4], acc2[4][4];
    #pragma unroll
    for (int i = 0; i < 4; i++)
        #pragma unroll
        for (int j = 0; j < 4; j++) { acc1[i][j] = 0ull; acc2[i][j] = 0ull; }

    int gr = row0 + lrow;
    bool valid = (gr < 5000);
    const float* aptr = Wv + ((tid < 128) ? (size_t)gr * K : (size_t)(5000 + gr) * K);
    int jcol = col0 + bCol;
    const float* bbase = (jcol < 256) ? (We + jcol) : (Wa + (jcol - 256));
    bool a_half = (tid < 128);

    // preload k-block 0 into buffer 0
    {
        float4 av = make_float4(0, 0, 0, 0);
        if (valid) av = __ldg((const float4*)(aptr + ak4));
        float (*As)[128] = a_half ? As1[0] : As2[0];
        *(float2*)&As[ak4 + 0][2 * lrow] = make_float2(av.x, av.x);
        *(float2*)&As[ak4 + 1][2 * lrow] = make_float2(av.y, av.y);
        *(float2*)&As[ak4 + 2][2 * lrow] = make_float2(av.z, av.z);
        *(float2*)&As[ak4 + 3][2 * lrow] = make_float2(av.w, av.w);
        *(float4*)&Bs[0][bK][bCol] = __ldg((const float4*)(bbase + bK * 256));
    }
    __syncthreads();

    for (int k0 = 0; k0 < K; k0 += 8) {
        int buf = (k0 >> 3) & 1;
        // issue next block's LDG early (hidden under compute)
        float4 av_n = make_float4(0, 0, 0, 0), bv_n;
        bool has_next = (k0 + 8 < K);
        if (has_next) {
            if (valid) av_n = __ldg((const float4*)(aptr + k0 + 8 + ak4));
            bv_n = __ldg((const float4*)(bbase + (k0 + 8 + bK) * 256));
        }
        #pragma unroll
        for (int kk = 0; kk < 8; kk++) {
            ull ra1[4], ra2[4], rb[4];
            #pragma unroll
            for (int i = 0; i < 4; i++) {
                ra1[i] = *(const ull*)&As1[buf][kk][2 * (ty * 4 + i)];
                ra2[i] = *(const ull*)&As2[buf][kk][2 * (ty * 4 + i)];
            }
            #pragma unroll
            for (int jp = 0; jp < 4; jp++) rb[jp] = *(const ull*)&Bs[buf][kk][jp * 32 + tx * 2];
            #pragma unroll
            for (int i = 0; i < 4; i++)
                #pragma unroll
                for (int jp = 0; jp < 4; jp++) {
                    acc1[i][jp] = fma2(ra1[i], rb[jp], acc1[i][jp]);
                    acc2[i][jp] = fma2(ra2[i], rb[jp], acc2[i][jp]);
                }
        }
        if (has_next) {   // store next block into the other buffer
            float (*As)[128] = a_half ? As1[buf ^ 1] : As2[buf ^ 1];
            *(float2*)&As[ak4 + 0][2 * lrow] = make_float2(av_n.x, av_n.x);
            *(float2*)&As[ak4 + 1][2 * lrow] = make_float2(av_n.y, av_n.y);
            *(float2*)&As[ak4 + 2][2 * lrow] = make_float2(av_n.z, av_n.z);
            *(float2*)&As[ak4 + 3][2 * lrow] = make_float2(av_n.w, av_n.w);
            *(float4*)&Bs[buf ^ 1][bK][bCol] = bv_n;
            __syncthreads();
        }
    }
    bool is_erase = (col0 < 256);
    #pragma unroll
    for (int i = 0; i < 4; i++) {
        int row = ty * 4 + i;
        int q = row0 + row;            // q_id - 1
        if (q >= 5000) continue;
        #pragma unroll
        for (int jp = 0; jp < 4; jp++) {
            int c = col0 + jp * 32 + tx * 2;
            float c1lo, c1hi, c2lo, c2hi;
            unpack2(acc1[i][jp], c1lo, c1hi);
            unpack2(acc2[i][jp], c2lo, c2hi);
            float blo = g_bvE2[c], bhi = g_bvE2[c + 1];
            float x1lo = c1lo + blo, x1hi = c1hi + bhi;
            #pragma unroll
            for (int rr = 0; rr < 4; rr++) {
                float sc = (float)rr * (1.0f / 3.0f);
                float xlo = fmaf(sc, c2lo, x1lo);
                float xhi = fmaf(sc, c2hi, x1hi);
                float olo = is_erase ? sigmoid_(xlo) : tanh_(xlo);
                float ohi = is_erase ? sigmoid_(xhi) : tanh_(xhi);
                *(float2*)&g_EAtab[((size_t)(q + 1) * 4 + rr) * 512 + c] = make_float2(olo, ohi);
            }
        }
    }
}

// ---------------- K3: persistent recurrence scan (ring + W reg pipeline) -----
__device__ __forceinline__ void ea_pref(int q, int r, int p, float2& ee, float2& aa) {
    const float* ea = g_EAtab + (size_t)(q * 4 + r) * 512;
    ee = __ldg((const float2*)(ea + 2 * p));
    aa = __ldg((const float2*)(ea + 256 + 2 * p));
}

__device__ __forceinline__ void ldW(ull* W, const float* src) {
    const ulonglong2* wp = (const ulonglong2*)src;
    ulonglong2 t0 = wp[0], t1 = wp[1], t2 = wp[2], t3 = wp[3];
    W[0] = t0.x; W[1] = t0.y; W[2] = t1.x; W[3] = t1.y;
    W[4] = t2.x; W[5] = t2.y; W[6] = t3.x; W[7] = t3.y;
}

__device__ __forceinline__ void scan_step(ull* R0, ull* R1, const ull* W,
                                          float2 ee, float2 aa,
                                          int quarter, float* outp) {
    ull ne0 = pack2(-ee.x, -ee.x), ne1 = pack2(-ee.y, -ee.y);
    ull a20 = pack2(aa.x, aa.x),   a21 = pack2(aa.y, aa.y);
    ull acc0a = 0ull, acc0b = 0ull, acc1a = 0ull, acc1b = 0ull;
    #pragma unroll
    for (int i = 0; i < 4; i++) {
        ull t0 = fma2(ne0, R0[i], a20);
        ull t1 = fma2(ne1, R1[i], a21);
        acc0a = fma2(W[i], R0[i], acc0a);
        acc1a = fma2(W[i], R1[i], acc1a);
        R0[i] = fma2(W[i], t0, R0[i]);
        R1[i] = fma2(W[i], t1, R1[i]);
    }
    #pragma unroll
    for (int i = 4; i < 8; i++) {
        ull t0 = fma2(ne0, R0[i], a20);
        ull t1 = fma2(ne1, R1[i], a21);
        acc0b = fma2(W[i], R0[i], acc0b);
        acc1b = fma2(W[i], R1[i], acc1b);
        R0[i] = fma2(W[i], t0, R0[i]);
        R1[i] = fma2(W[i], t1, R1[i]);
    }
    float x0a, y0a, x0b, y0b, x1a, y1a, x1b, y1b;
    unpack2(acc0a, x0a, y0a); unpack2(acc0b, x0b, y0b);
    unpack2(acc1a, x1a, y1a); unpack2(acc1b, x1b, y1b);
    float rd0 = (x0a + x0b) + (y0a + y0b);
    float rd1 = (x1a + x1b) + (y1a + y1b);
    rd0 += __shfl_xor_sync(0xffffffffu, rd0, 1);
    rd0 += __shfl_xor_sync(0xffffffffu, rd0, 2);
    rd1 += __shfl_xor_sync(0xffffffffu, rd1, 1);
    rd1 += __shfl_xor_sync(0xffffffffu, rd1, 2);
    if (quarter == 0) *(float2*)outp = make_float2(rd0, rd1);
}

__global__ void __launch_bounds__(512) scan_kernel(const int* __restrict__ q_data,
                                                   const int* __restrict__ r_data,
                                                   const float* __restrict__ initMv) {
    const int b = blockIdx.x;
    const int tid = threadIdx.x;
    const int quarter = tid & 3;
    const int p = tid >> 2;

    __shared__ int q_sh[SS + 8];
    __shared__ int r_sh[SS + 8];
    __shared__ float wring[64 * MSLOT];   // 64 steps x 64 floats = 16KB

    for (int i = tid; i < SS; i += 512) {
        q_sh[i] = q_data[b * SS + i];
        r_sh[i] = r_data[b * SS + i];
    }
    if (tid < 8) {
        q_sh[SS + tid] = q_data[b * SS + SS - 1];
        r_sh[SS + tid] = r_data[b * SS + SS - 1];
    }

    ull R0[8], R1[8];
    #pragma unroll
    for (int i = 0; i < 8; i++) {
        int m = quarter * 16 + 2 * i;
        R0[i] = pack2(initMv[m * VDIM + 2 * p],     initMv[(m + 1) * VDIM + 2 * p]);
        R1[i] = pack2(initMv[m * VDIM + 2 * p + 1], initMv[(m + 1) * VDIM + 2 * p + 1]);
    }
    __syncthreads();

    float2 eA, aA, eB, aB, eC, aC, eD, aD;
    ea_pref(q_sh[0], r_sh[0], p, eA, aA);
    ea_pref(q_sh[1], r_sh[1], p, eB, aB);
    ea_pref(q_sh[2], r_sh[2], p, eC, aC);

    float* rdbase = g_read + (((size_t)b << 10)) * VDIM + 2 * p;
    const int qoff = quarter * 16;

    ull W0[8], W1[8];

    #pragma unroll 1
    for (int c = 0; c < 16; c++) {
        __syncthreads();
        {   // cooperative refill: 64 steps x 64 floats, 2 float4 per thread
            int u = tid * 2;
            int sl = u >> 4;
            int fi = u & 15;
            const float* src = g_Wtab + q_sh[c * 64 + sl] * MSLOT;
            *(float4*)&wring[sl * MSLOT + fi * 4]       = __ldg((const float4*)(src + fi * 4));
            *(float4*)&wring[sl * MSLOT + (fi + 1) * 4] = __ldg((const float4*)(src + (fi + 1) * 4));
        }
        __syncthreads();
        int base = c * 64;
        ldW(W0, &wring[qoff]);
        #pragma unroll 1
        for (int k = 0; k < 16; k++) {
            int s = base + 4 * k;
            int sl = 4 * k;
            ldW(W1, &wring[(sl + 1) * MSLOT + qoff]);
            ea_pref(q_sh[s + 3], r_sh[s + 3], p, eD, aD);
            scan_step(R0, R1, W0, eA, aA, quarter, rdbase + (size_t)s * VDIM);

            ldW(W0, &wring[(sl + 2) * MSLOT + qoff]);
            ea_pref(q_sh[s + 4], r_sh[s + 4], p, eA, aA);
            scan_step(R0, R1, W1, eB, aB, quarter, rdbase + (size_t)(s + 1) * VDIM);

            ldW(W1, &wring[(sl + 3) * MSLOT + qoff]);
            ea_pref(q_sh[s + 5], r_sh[s + 5], p, eB, aB);
            scan_step(R0, R1, W0, eC, aC, quarter, rdbase + (size_t)(s + 2) * VDIM);

            ldW(W0, &wring[((sl + 4) & 63) * MSLOT + qoff]);
            ea_pref(q_sh[s + 6], r_sh[s + 6], p, eC, aC);
            scan_step(R0, R1, W1, eD, aD, quarter, rdbase + (size_t)(s + 3) * VDIM);
        }
    }
}

// ---------------- K4: summary SGEMM + fused theta/disc (double-buffered) -----
__global__ void __launch_bounds__(256) sgemm_sum_kernel(const int* __restrict__ q_data,
                                                        const float* __restrict__ W_summary,
                                                        const float* __restrict__ W_theta,
                                                        const float* __restrict__ W_disc) {
    const int K = 256, N = 128;
    __shared__ float As[2][8][256];   // duplicated
    __shared__ float Bs[2][8][128];
    __shared__ int qrow_s[128];
    __shared__ float sWth[128], sWd[128];
    int tid = threadIdx.x;
    int row0 = blockIdx.x * 128;
    if (tid < 128) {
        qrow_s[tid] = q_data[row0 + tid];
        sWth[tid] = W_theta[tid];
        sWd[tid] = W_disc[tid];
    }
    int aRow = tid >> 1, aK4 = (tid & 1) * 4;
    int bK = tid >> 5, bCol = (tid & 31) * 4;
    int tx = tid & 15, ty = tid >> 4;
    ull acc2[8][4];
    #pragma unroll
    for (int i = 0; i < 8; i++)
        #pragma unroll
        for (int j = 0; j < 4; j++) acc2[i][j] = 0ull;

    const float* A = g_read + (size_t)(row0 + aRow) * K + aK4;
    // preload k-block 0 into buffer 0
    {
        float4 av = __ldg((const float4*)A);
        As[0][aK4 + 0][2 * aRow] = av.x; As[0][aK4 + 0][2 * aRow + 1] = av.x;
        As[0][aK4 + 1][2 * aRow] = av.y; As[0][aK4 + 1][2 * aRow + 1] = av.y;
        As[0][aK4 + 2][2 * aRow] = av.z; As[0][aK4 + 2][2 * aRow + 1] = av.z;
        As[0][aK4 + 3][2 * aRow] = av.w; As[0][aK4 + 3][2 * aRow + 1] = av.w;
        *(float4*)&Bs[0][bK][bCol] = __ldg((const float4*)(W_summary + bK * N + bCol));
    }
    __syncthreads();

    for (int k0 = 0; k0 < K; k0 += 8) {
        int buf = (k0 >> 3) & 1;
        float4 av_n, bv_n;
        bool has_next = (k0 + 8 < K);
        if (has_next) {
            av_n = __ldg((const float4*)(A + k0 + 8));
            bv_n = __ldg((const float4*)(W_summary + (k0 + 8 + bK) * N + bCol));
        }
        #pragma unroll
        for (int kk = 0; kk < 8; kk++) {
            ull ra[8], rb[4];
            #pragma unroll
            for (int i = 0; i < 8; i++) ra[i] = *(const ull*)&As[buf][kk][2 * (ty * 8 + i)];
            #pragma unroll
            for (int jp = 0; jp < 4; jp++) rb[jp] = *(const ull*)&Bs[buf][kk][jp * 32 + tx * 2];
            #pragma unroll
            for (int i = 0; i < 8; i++)
                #pragma unroll
                for (int jp = 0; jp < 4; jp++)
                    acc2[i][jp] = fma2(ra[i], rb[jp], acc2[i][jp]);
        }
        if (has_next) {
            int nb = buf ^ 1;
            As[nb][aK4 + 0][2 * aRow] = av_n.x; As[nb][aK4 + 0][2 * aRow + 1] = av_n.x;
            As[nb][aK4 + 1][2 * aRow] = av_n.y; As[nb][aK4 + 1][2 * aRow + 1] = av_n.y;
            As[nb][aK4 + 2][2 * aRow] = av_n.z; As[nb][aK4 + 2][2 * aRow + 1] = av_n.z;
            As[nb][aK4 + 3][2 * aRow] = av_n.w; As[nb][aK4 + 3][2 * aRow + 1] = av_n.w;
            *(float4*)&Bs[nb][bK][bCol] = bv_n;
            __syncthreads();
        }
    }
    // Epilogue: tanh + project to (theta, disc) partials, reduce over 16 tx lanes.
    #pragma unroll
    for (int i = 0; i < 8; i++) {
        int rl = ty * 8 + i;
        int r = row0 + rl;
        int q = qrow_s[rl];
        const float* qs = g_QStab + q * FDIM;
        float thp = 0.0f, dpp = 0.0f;
        #pragma unroll
        for (int jp = 0; jp < 4; jp++) {
            int c = jp * 32 + tx * 2;
            float lo, hi; unpack2(acc2[i][jp], lo, hi);
            float s_lo = tanh_(lo + __ldg(qs + c));
            float s_hi = tanh_(hi + __ldg(qs + c + 1));
            thp = fmaf(s_lo, sWth[c], thp);
            thp = fmaf(s_hi, sWth[c + 1], thp);
            dpp = fmaf(s_lo, sWd[c], dpp);
            dpp = fmaf(s_hi, sWd[c + 1], dpp);
        }
        #pragma unroll
        for (int o = 8; o; o >>= 1) {
            thp += __shfl_xor_sync(0xffffffffu, thp, o);
            dpp += __shfl_xor_sync(0xffffffffu, dpp, o);
        }
        if (tx == 0) *(float2*)&g_thdp[(size_t)r * 2] = make_float2(thp, dpp);
    }
}

// ---------------- K5: per-token head (theta/alpha/CORAL), 32 tokens/warp -----
__global__ void __launch_bounds__(256) head_kernel(const int* __restrict__ q_data,
                                                   const float* __restrict__ b_theta,
                                                   const float* __restrict__ b_disc,
                                                   const float* __restrict__ W_c1,
                                                   const float* __restrict__ b_c1,
                                                   const float* __restrict__ W_c2,
                                                   const float* __restrict__ b_c2,
                                                   const float* __restrict__ coral_w,
                                                   const float* __restrict__ coral_b,
                                                   float* __restrict__ out) {
    __shared__ float sWc1[5 * 64], sBc1[64], sWc2[64 * 32], sBc2[32], sCw[32];
    __shared__ float h1s[8][64];
    int tid = threadIdx.x;
    for (int i = tid; i < 320; i += 256) sWc1[i] = W_c1[i];
    for (int i = tid; i < 2048; i += 256) sWc2[i] = W_c2[i];
    if (tid < 64) sBc1[tid] = b_c1[tid];
    if (tid < 32) { sBc2[tid] = b_c2[tid]; sCw[tid] = coral_w[tid]; }
    __syncthreads();

    int warp = tid >> 5, lane = tid & 31;
    float bth = b_theta[0], bd = b_disc[0];
    float cb0 = coral_b[0], cb1 = coral_b[1], cb2 = coral_b[2];
    float cw = sCw[lane];

    const int TOK = 32;
    size_t base = ((size_t)blockIdx.x * 8 + warp) * TOK;
    for (int t = 0; t < TOK; t++) {
        size_t n = base + t;
        float2 td = *(const float2*)&g_thdp[n * 2];   // broadcast load
        float theta = (td.x + bth) * 3.0f;
        int q = q_data[n];
        float alpha = softplusf_(td.y + g_qdtab[q] + bd);
        float be0 = g_betatab[q * 3 + 0];
        float be1 = g_betatab[q * 3 + 1];
        float be2 = g_betatab[q * 3 + 2];
        float feat[5] = {theta, alpha, be0, be1, be2};

        float h1a = sBc1[lane], h1b = sBc1[lane + 32];
        #pragma unroll
        for (int i = 0; i < 5; i++) {
            h1a = fmaf(feat[i], sWc1[i * 64 + lane], h1a);
            h1b = fmaf(feat[i], sWc1[i * 64 + lane + 32], h1b);
        }
        h1s[warp][lane] = fmaxf(h1a, 0.0f);
        h1s[warp][lane + 32] = fmaxf(h1b, 0.0f);
        __syncwarp();
        float h2 = sBc2[lane];
        #pragma unroll
        for (int i = 0; i < 64; i++) h2 = fmaf(h1s[warp][i], sWc2[i * 32 + lane], h2);
        h2 = fmaxf(h2, 0.0f);
        float lg = h2 * cw;
        #pragma unroll
        for (int o = 16; o; o >>= 1) lg += __shfl_xor_sync(0xffffffffu, lg, o);

        if (lane == 0) {
            float l0 = lg + cb0, l1 = lg + cb1, l2 = lg + cb2;
            float c1 = sigmoid_(l0);
            float c2 = c1 * sigmoid_(l1);
            float c3 = c2 * sigmoid_(l2);
            const size_t N = NT;
            out[n] = theta;
            out[N + n * 3 + 0] = be0;
            out[N + n * 3 + 1] = be1;
            out[N + n * 3 + 2] = be2;
            out[4 * N + n] = alpha;
            out[5 * N + n * 4 + 0] = 1.0f - c1;
            out[5 * N + n * 4 + 1] = c1 - c2;
            out[5 * N + n * 4 + 2] = c2 - c3;
            out[5 * N + n * 4 + 3] = c3;
            out[9 * N + n * 3 + 0] = l0;
            out[9 * N + n * 3 + 1] = l1;
            out[9 * N + n * 3 + 2] = l2;
        }
        __syncwarp();
    }
}

// ---------------- launch -----------------------------------------------------
extern "C" void kernel_launch(void* const* d_in, const int* in_sizes, int n_in,
                              void* d_out, int out_size) {
    const int*   q_data   = (const int*)d_in[0];
    const int*   r_data   = (const int*)d_in[1];
    const float* qe_table = (const float*)d_in[2];
    const float* key_mem  = (const float*)d_in[3];
    const float* initMv   = (const float*)d_in[4];
    const float* W_value  = (const float*)d_in[5];
    const float* b_value  = (const float*)d_in[6];
    const float* W_erase  = (const float*)d_in[7];
    const float* b_erase  = (const float*)d_in[8];
    const float* W_add    = (const float*)d_in[9];
    const float* b_add    = (const float*)d_in[10];
    const float* W_summary= (const float*)d_in[11];
    const float* b_summary= (const float*)d_in[12];
    const float* W_theta  = (const float*)d_in[13];
    const float* b_theta  = (const float*)d_in[14];
    const float* W_beta   = (const float*)d_in[15];
    const float* b_beta   = (const float*)d_in[16];
    const float* W_disc   = (const float*)d_in[17];
    const float* b_disc   = (const float*)d_in[18];
    const float* W_c1     = (const float*)d_in[19];
    const float* b_c1     = (const float*)d_in[20];
    const float* W_c2     = (const float*)d_in[21];
    const float* b_c2     = (const float*)d_in[22];
    const float* coral_w  = (const float*)d_in[23];
    const float* coral_b  = (const float*)d_in[24];
    float* out = (float*)d_out;

    // L1: wtab + perq + bv
    wtab_perq_kernel<<<WTAB_BLOCKS + 1, 128>>>(qe_table, key_mem, W_summary, b_summary,
                                               W_beta, b_beta, W_disc,
                                               b_value, W_erase, W_add, b_erase, b_add);
    // L2: fused PP GEMM + EA table
    {
        dim3 g(4, 79);
        ppea_kernel<<<g, 256>>>(W_value, W_erase, W_add);
    }
    // L3: scan
    scan_kernel<<<BB, 512>>>(q_data, r_data, initMv);
    // L4: summary GEMM + theta/disc fusion (<- ncu capture slot)
    sgemm_sum_kernel<<<NT / 128, 256>>>(q_data, W_summary, W_theta, W_disc);
    // L5: head
    head_kernel<<<NT / (8 * 32), 256>>>(q_data, b_theta, b_disc,
                                        W_c1, b_c1, W_c2, b_c2, coral_w, coral_b, out);
}